// round 15
// baseline (speedup 1.0000x reference)
#include <cuda_runtime.h>
#include <cuda_bf16.h>

#define NCTA   128
#define TPB    256
#define PP     1024
#define DD     32
#define RS     1032
#define WS     520               /* t-cache u32 words per row (padded) */
#define MAXIT  30
#define EPSV   0.1f
#define LN2F   0.69314718055994530942f
#define ALPHA  14.4269504088896340736f   /* 1/(eps*ln2) */
#define THRESH 0.1f

typedef unsigned long long u64;

__device__ unsigned          g_cnt = 0;
__device__ volatile unsigned g_gen = 0;
__device__ float2 g_pm[NCTA * PP];                 // iter-0 (max,sum) partials
__device__ float  g_csum[MAXIT * 4 * PP];          // per-iter per-batch col sums (atomic)
__device__ float  g_errb[MAXIT * 4 * 8];           // per-iter per-batch err (padded)
__device__ float  g_b2[4 * PP];                    // B after iter 0
__device__ double g_costp[NCTA];

struct Smem {
    float    K2[32 * RS];      // 132096 B
    unsigned tb[32 * WS];      // 66560 B bf16x2 t-cache (doubles as setup staging)
    float    bb[PP];           // current B (local)
    float    lnu2[PP];
    double   redd[TPB];
    float2   cmb[8][32];       // iter-0 combine tree
    float    A2s[32];
    float    lmu2s[32];
    float    muLin[32];
    float    rowShift[32];
    float    wAs[32];
    float    errw[8];
    float    err4[4];
    float    Sx, Sy;
};

__device__ __forceinline__ float ex2f(float x){ float r; asm("ex2.approx.ftz.f32 %0, %1;" : "=f"(r) : "f"(x)); return r; }
__device__ __forceinline__ float lg2f(float x){ float r; asm("lg2.approx.f32 %0, %1;" : "=f"(r) : "f"(x)); return r; }
__device__ __forceinline__ u64 pk2(float lo, float hi){ u64 r; asm("mov.b64 %0, {%1, %2};" : "=l"(r) : "f"(lo), "f"(hi)); return r; }
__device__ __forceinline__ void upk2(u64 v, float& lo, float& hi){ asm("mov.b64 {%0, %1}, %2;" : "=f"(lo), "=f"(hi) : "l"(v)); }
__device__ __forceinline__ void fma2(u64& d, u64 a, u64 b){ asm("fma.rn.f32x2 %0, %1, %2, %0;" : "+l"(d) : "l"(a), "l"(b)); }
__device__ __forceinline__ u64 add2(u64 a, u64 b){ u64 r; asm("add.rn.f32x2 %0, %1, %2;" : "=l"(r) : "l"(a), "l"(b)); return r; }
__device__ __forceinline__ unsigned pkbf(float lo, float hi){
    unsigned r; asm("cvt.rn.bf16x2.f32 %0, %1, %2;" : "=r"(r) : "f"(hi), "f"(lo)); return r;
}
__device__ __forceinline__ float2 upbf(unsigned w){
    __nv_bfloat162 h = *reinterpret_cast<__nv_bfloat162*>(&w);
    return __bfloat1622float2(h);
}

// R3-style global barrier: single atomic counter + single generation flag.
__device__ __forceinline__ void gbar(unsigned target) {
    __syncthreads();
    if (threadIdx.x == 0) {
        __threadfence();
        if (atomicAdd(&g_cnt, 1u) == NCTA - 1u) {
            g_cnt = 0;
            __threadfence();
            g_gen = target;
        } else {
            while (g_gen != target) { }
            __threadfence();
        }
    }
    __syncthreads();
}

__global__ void __launch_bounds__(TPB, 1)
sinkhorn_kernel(const float* __restrict__ gx, const float* __restrict__ gy,
                const float* __restrict__ gxw, const float* __restrict__ gyw,
                float* __restrict__ gout)
{
    extern __shared__ __align__(16) char smraw[];
    Smem* S = reinterpret_cast<Smem*>(smraw);

    const int tid  = threadIdx.x;
    const int lane = tid & 31;
    const int warp = tid >> 5;       // 0..7
    const int bid  = blockIdx.x;
    const int nb   = bid >> 5;
    const int sub  = bid & 31;
    const int r0   = sub * 32;

    unsigned tgt = g_gen;    // quiescent base; read before any release

    // ---- zero per-launch atomic accumulators (disjoint slices) ----
    for (int k = bid * TPB + tid; k < MAXIT * 4 * PP; k += NCTA * TPB)
        g_csum[k] = 0.f;
    if (bid == 0)
        for (int k = tid; k < MAXIT * 4 * 8; k += TPB) g_errb[k] = 0.f;

    // ---- global weight sums (redundant per CTA, deterministic) ----
    {
        float px = 0.f, py = 0.f;
        for (int k = tid; k < 4096; k += TPB) { px += gxw[k]; py += gyw[k]; }
        S->redd[tid] = (double)px; __syncthreads();
        for (int s = TPB/2; s > 0; s >>= 1) { if (tid < s) S->redd[tid] += S->redd[tid+s]; __syncthreads(); }
        if (tid == 0) S->Sx = (float)S->redd[0];
        __syncthreads();
        S->redd[tid] = (double)py; __syncthreads();
        for (int s = TPB/2; s > 0; s >>= 1) { if (tid < s) S->redd[tid] += S->redd[tid+s]; __syncthreads(); }
        if (tid == 0) S->Sy = (float)S->redd[0];
        __syncthreads();
    }

    if (tid < 32) {
        float mu = gxw[nb * PP + r0 + tid] / S->Sx + 1e-8f;
        S->muLin[tid] = mu;
        S->lmu2s[tid] = lg2f(mu);
        S->A2s[tid]   = 0.f;
    }
    for (int c = tid; c < PP; c += TPB)
        S->lnu2[c] = lg2f(gyw[nb * PP + c] / S->Sy + 1e-8f);

    // ---- build K2 = -C/(eps*ln2) in SMEM ----
    const float* ybase = gy + (size_t)nb * PP * DD;
    for (int c = tid; c < PP; c += TPB) {
        const float4* yc = (const float4*)(ybase + c * DD);
        float s = 0.f;
#pragma unroll
        for (int q = 0; q < 8; q++) { float4 v = yc[q]; s += v.x*v.x + v.y*v.y + v.z*v.z + v.w*v.w; }
        S->bb[c] = s * ALPHA;   // temp: ALPHA*|y|^2
    }
    float xv[32];
    {
        const float4* xr = (const float4*)(gx + (size_t)(nb * PP + r0 + lane) * DD);
#pragma unroll
        for (int q = 0; q < 8; q++) {
            float4 v = xr[q];
            xv[4*q] = v.x; xv[4*q+1] = v.y; xv[4*q+2] = v.z; xv[4*q+3] = v.w;
        }
    }
    float x2 = 0.f;
#pragma unroll
    for (int d = 0; d < 32; d++) x2 += xv[d] * xv[d];
    const float cx = ALPHA * x2;
    u64 xp[16];
#pragma unroll
    for (int q = 0; q < 16; q++) xp[q] = pk2(xv[2*q], xv[2*q+1]);
    __syncthreads();

    for (int chunk = 0; chunk < 4; chunk++) {
        const int j0 = chunk * 256;
        const float4* ysrc = (const float4*)(ybase + j0 * DD);
        float4* yst = (float4*)S->tb;    // alias t-cache as staging during setup
#pragma unroll
        for (int q = 0; q < 8; q++) yst[tid + 256 * q] = ysrc[tid + 256 * q];
        __syncthreads();
#pragma unroll 4
        for (int m = 0; m < 32; m++) {
            const int jj = warp + 8 * m;
            const ulonglong2* yp = (const ulonglong2*)((float*)S->tb + jj * DD);
            u64 acc[4] = {0ull, 0ull, 0ull, 0ull};
#pragma unroll
            for (int q = 0; q < 8; q++) {
                ulonglong2 w = yp[q];
                fma2(acc[(2*q)   & 3], xp[2*q],     w.x);
                fma2(acc[(2*q+1) & 3], xp[2*q + 1], w.y);
            }
            u64 st = add2(add2(acc[0], acc[1]), add2(acc[2], acc[3]));
            float lo, hi; upk2(st, lo, hi);
            float dot = lo + hi;
            S->K2[lane * RS + j0 + jj] = fmaf(dot, 2.f * ALPHA, -(cx + S->bb[j0 + jj]));
        }
        __syncthreads();
    }

    // row maxes (iter-0 shift; exact since B=0 at iter 0)
#pragma unroll
    for (int k = 0; k < 4; k++) {
        const int r = warp * 4 + k;
        const float4* kr = (const float4*)(S->K2 + r * RS);
        float m = -1e30f;
#pragma unroll
        for (int q = 0; q < 8; q++) {
            float4 a = kr[lane + 32 * q];
            m = fmaxf(m, fmaxf(fmaxf(a.x, a.y), fmaxf(a.z, a.w)));
        }
#pragma unroll
        for (int o = 16; o; o >>= 1) m = fmaxf(m, __shfl_xor_sync(0xffffffffu, m, o));
        if (lane == 0) S->rowShift[r] = m;
    }
#pragma unroll
    for (int cc = 0; cc < 4; cc++) S->bb[tid + 256 * cc] = 0.f;

    gbar(++tgt);   // accumulator zeroing visible before any atomicAdd

    const int c0 = 2 * tid, c1 = 2 * tid + 1, c2 = 2 * tid + 512, c3 = 2 * tid + 513;

    // ================= Sinkhorn iterations =================
    int iter = 0;
    for (;;) {
        // ---------- row pass: t = 2^(K2+B-m) -> bf16 cache; rowsum; A update ----------
        {
            const float4* b4 = (const float4*)S->bb;
            const int rb = warp * 4;
            const float4* kr0 = (const float4*)(S->K2 + (rb + 0) * RS);
            const float4* kr1 = (const float4*)(S->K2 + (rb + 1) * RS);
            const float4* kr2 = (const float4*)(S->K2 + (rb + 2) * RS);
            const float4* kr3 = (const float4*)(S->K2 + (rb + 3) * RS);
            uint2* t0 = (uint2*)(S->tb + (rb + 0) * WS);
            uint2* t1 = (uint2*)(S->tb + (rb + 1) * WS);
            uint2* t2 = (uint2*)(S->tb + (rb + 2) * WS);
            uint2* t3 = (uint2*)(S->tb + (rb + 3) * WS);
            const float m0 = S->rowShift[rb + 0];
            const float m1 = S->rowShift[rb + 1];
            const float m2 = S->rowShift[rb + 2];
            const float m3 = S->rowShift[rb + 3];
            float s0 = 0.f, s1 = 0.f, s2 = 0.f, s3 = 0.f;
#pragma unroll
            for (int q = 0; q < 8; q++) {
                const int ix = lane + 32 * q;
                float4 b = b4[ix];
                {
                    float4 a = kr0[ix];
                    float ta = ex2f(a.x + b.x - m0), tb_ = ex2f(a.y + b.y - m0);
                    float tc = ex2f(a.z + b.z - m0), td = ex2f(a.w + b.w - m0);
                    s0 += (ta + tb_) + (tc + td);
                    t0[ix] = make_uint2(pkbf(ta, tb_), pkbf(tc, td));
                }
                {
                    float4 a = kr1[ix];
                    float ta = ex2f(a.x + b.x - m1), tb_ = ex2f(a.y + b.y - m1);
                    float tc = ex2f(a.z + b.z - m1), td = ex2f(a.w + b.w - m1);
                    s1 += (ta + tb_) + (tc + td);
                    t1[ix] = make_uint2(pkbf(ta, tb_), pkbf(tc, td));
                }
                {
                    float4 a = kr2[ix];
                    float ta = ex2f(a.x + b.x - m2), tb_ = ex2f(a.y + b.y - m2);
                    float tc = ex2f(a.z + b.z - m2), td = ex2f(a.w + b.w - m2);
                    s2 += (ta + tb_) + (tc + td);
                    t2[ix] = make_uint2(pkbf(ta, tb_), pkbf(tc, td));
                }
                {
                    float4 a = kr3[ix];
                    float ta = ex2f(a.x + b.x - m3), tb_ = ex2f(a.y + b.y - m3);
                    float tc = ex2f(a.z + b.z - m3), td = ex2f(a.w + b.w - m3);
                    s3 += (ta + tb_) + (tc + td);
                    t3[ix] = make_uint2(pkbf(ta, tb_), pkbf(tc, td));
                }
            }
#pragma unroll
            for (int o = 16; o; o >>= 1) {
                s0 += __shfl_xor_sync(0xffffffffu, s0, o);
                s1 += __shfl_xor_sync(0xffffffffu, s1, o);
                s2 += __shfl_xor_sync(0xffffffffu, s2, o);
                s3 += __shfl_xor_sync(0xffffffffu, s3, o);
            }
            if (lane == 0) {
                float lse0 = m0 + lg2f(s0), lse1 = m1 + lg2f(s1);
                float lse2 = m2 + lg2f(s2), lse3 = m3 + lg2f(s3);
                float a0 = S->lmu2s[rb+0] - lse0, a1 = S->lmu2s[rb+1] - lse1;
                float a2 = S->lmu2s[rb+2] - lse2, a3 = S->lmu2s[rb+3] - lse3;
                S->errw[warp] = fabsf(a0 - S->A2s[rb+0]) + fabsf(a1 - S->A2s[rb+1])
                              + fabsf(a2 - S->A2s[rb+2]) + fabsf(a3 - S->A2s[rb+3]);
                S->A2s[rb+0] = a0; S->A2s[rb+1] = a1; S->A2s[rb+2] = a2; S->A2s[rb+3] = a3;
                S->rowShift[rb+0] = lse0; S->rowShift[rb+1] = lse1;
                S->rowShift[rb+2] = lse2; S->rowShift[rb+3] = lse3;
                S->wAs[rb+0] = S->muLin[rb+0] / s0;
                S->wAs[rb+1] = S->muLin[rb+1] / s1;
                S->wAs[rb+2] = S->muLin[rb+2] / s2;
                S->wAs[rb+3] = S->muLin[rb+3] / s3;
            }
        }
        __syncthreads();
        if (tid == 0) {
            float e = ((S->errw[0] + S->errw[1]) + (S->errw[2] + S->errw[3]))
                    + ((S->errw[4] + S->errw[5]) + (S->errw[6] + S->errw[7]));
            atomicAdd(&g_errb[(iter * 4 + nb) * 8], e);
        }

        // ---------- column reduction ----------
        if (iter == 0) {
            // exact max-shifted path (handles extreme column dynamic range at B=0)
            float m0=-1e30f, m1=-1e30f, m2=-1e30f, m3=-1e30f;
#pragma unroll
            for (int r = 0; r < 32; r++) {
                const float ar = S->A2s[r];
                const float* kr = S->K2 + r * RS;
                float2 ka = *(const float2*)(kr + c0);
                float2 kb = *(const float2*)(kr + c2);
                m0 = fmaxf(m0, ka.x + ar); m1 = fmaxf(m1, ka.y + ar);
                m2 = fmaxf(m2, kb.x + ar); m3 = fmaxf(m3, kb.y + ar);
            }
            float s0=0.f, s1=0.f, s2=0.f, s3=0.f;
#pragma unroll
            for (int r = 0; r < 32; r++) {
                const float ar = S->A2s[r];
                const float* kr = S->K2 + r * RS;
                float2 ka = *(const float2*)(kr + c0);
                float2 kb = *(const float2*)(kr + c2);
                s0 += ex2f(ka.x + (ar - m0)); s1 += ex2f(ka.y + (ar - m1));
                s2 += ex2f(kb.x + (ar - m2)); s3 += ex2f(kb.y + (ar - m3));
            }
            float2* pm = g_pm + (size_t)bid * PP;
            *(float4*)(pm + c0) = make_float4(m0, s0, m1, s1);
            *(float4*)(pm + c2) = make_float4(m2, s2, m3, s3);
            gbar(++tgt);

            // tree combine own 32 columns -> B -> g_b2
            {
                const float2* cpb = g_pm + (size_t)(nb * 32) * PP + (sub * 32 + lane);
                float2 p = __ldcg(cpb + warp * PP);
#pragma unroll
                for (int k = 1; k < 4; k++) {
                    float2 q = __ldcg(cpb + (warp + 8 * k) * PP);
                    float mn = fmaxf(p.x, q.x);
                    p.y = p.y * ex2f(p.x - mn) + q.y * ex2f(q.x - mn);
                    p.x = mn;
                }
                S->cmb[warp][lane] = p;
            }
            __syncthreads();
            if (warp == 0) {
                float2 p = S->cmb[0][lane];
#pragma unroll
                for (int w = 1; w < 8; w++) {
                    float2 q = S->cmb[w][lane];
                    float mn = fmaxf(p.x, q.x);
                    p.y = p.y * ex2f(p.x - mn) + q.y * ex2f(q.x - mn);
                    p.x = mn;
                }
                float B = S->lnu2[sub * 32 + lane] - (p.x + lg2f(p.y));
                __stcg(&g_b2[nb * PP + sub * 32 + lane], B);
            }
            gbar(++tgt);
            ((float4*)S->bb)[tid] = __ldcg(((const float4*)(g_b2 + nb * PP)) + tid);
        } else {
            // factorized pure-FMA column pass over cached bf16 t
            float s0 = 0.f, s1 = 0.f, s2 = 0.f, s3 = 0.f;
#pragma unroll 8
            for (int r = 0; r < 32; r++) {
                const float w = S->wAs[r];
                float2 fa = upbf(S->tb[r * WS + tid]);
                float2 fb = upbf(S->tb[r * WS + tid + 256]);
                s0 = fmaf(fa.x, w, s0);
                s1 = fmaf(fa.y, w, s1);
                s2 = fmaf(fb.x, w, s2);
                s3 = fmaf(fb.y, w, s3);
            }
            float* cs = g_csum + (size_t)(iter * 4 + nb) * PP;
            atomicAdd(cs + c0, s0);
            atomicAdd(cs + c1, s1);
            atomicAdd(cs + c2, s2);
            atomicAdd(cs + c3, s3);
            gbar(++tgt);

            // local B update: B_new = B_old + lnu - log2(S)
            const int c4 = 4 * tid;
            float4 sv = __ldcg((const float4*)(g_csum + (size_t)(iter * 4 + nb) * PP + c4));
            float4 bo = *(float4*)(S->bb + c4);
            bo.x += S->lnu2[c4 + 0] - lg2f(sv.x);
            bo.y += S->lnu2[c4 + 1] - lg2f(sv.y);
            bo.z += S->lnu2[c4 + 2] - lg2f(sv.z);
            bo.w += S->lnu2[c4 + 3] - lg2f(sv.w);
            *(float4*)(S->bb + c4) = bo;
        }

        // ---------- err gather + decide ----------
        if (tid < 4) S->err4[tid] = __ldcg(&g_errb[(iter * 4 + tid) * 8]);
        __syncthreads();
        float ev = (S->err4[0] + S->err4[1]) + (S->err4[2] + S->err4[3]);

        iter++;
        if (iter >= MAXIT) break;
        if (ev * (EPSV * LN2F * 0.25f) < THRESH) break;
    }

    // ---- final cost: cost_n = -eps*ln2 * sum 2^(K2+A+B) * K2 ----
    {
        const float bc0 = S->bb[c0], bc1 = S->bb[c1];
        const float bc2 = S->bb[c2], bc3 = S->bb[c3];
        float acc = 0.f;
#pragma unroll 8
        for (int r = 0; r < 32; r++) {
            const float ar = S->A2s[r];
            const float* kr = S->K2 + r * RS;
            float2 ka = *(const float2*)(kr + c0);
            float2 kb = *(const float2*)(kr + c2);
            acc = fmaf(ex2f(ka.x + ar + bc0), ka.x, acc);
            acc = fmaf(ex2f(ka.y + ar + bc1), ka.y, acc);
            acc = fmaf(ex2f(kb.x + ar + bc2), kb.x, acc);
            acc = fmaf(ex2f(kb.y + ar + bc3), kb.y, acc);
        }
        S->redd[tid] = (double)acc; __syncthreads();
        for (int s = TPB/2; s > 0; s >>= 1) { if (tid < s) S->redd[tid] += S->redd[tid+s]; __syncthreads(); }
        if (tid == 0) __stcg(&g_costp[bid], S->redd[0]);
    }
    gbar(++tgt);
    if (sub == 0 && warp == 0) {
        double cv = __ldcg(&g_costp[nb * 32 + lane]);
#pragma unroll
        for (int o = 16; o; o >>= 1)
            cv += __shfl_xor_sync(0xffffffffu, cv, o);
        if (lane == 0)
            gout[nb] = (float)(-(double)EPSV * (double)LN2F * cv);
    }
}

extern "C" void kernel_launch(void* const* d_in, const int* in_sizes, int n_in,
                              void* d_out, int out_size) {
    const float* x  = (const float*)d_in[0];
    const float* y  = (const float*)d_in[1];
    const float* xw = (const float*)d_in[2];
    const float* yw = (const float*)d_in[3];
    float* out = (float*)d_out;
    size_t smem = sizeof(Smem);
    cudaFuncSetAttribute(sinkhorn_kernel, cudaFuncAttributeMaxDynamicSharedMemorySize, (int)smem);
    sinkhorn_kernel<<<NCTA, TPB, smem>>>(x, y, xw, yw, out);
}